// round 1
// baseline (speedup 1.0000x reference)
#include <cuda_runtime.h>
#include <math.h>

#define Bq    4
#define Cc    64
#define Hh    256
#define Ww    256
#define W2    128
#define NPIX  65536   // Hh*Ww
#define NS    32768   // Hh*W2
#define NHEAD 4
#define Dd    16
#define C2    128
#define C4    256

// ---------------- scratch (device globals; no runtime allocation) ----------------
__device__ float g_qpre[(size_t)Bq*Cc*NPIX];
__device__ float g_kpre[(size_t)Bq*Cc*NPIX];
__device__ float g_vpre[(size_t)Bq*Cc*NPIX];
__device__ float g_qs  [(size_t)Bq*Cc*NS];
__device__ float g_ks  [(size_t)Bq*Cc*NS];
__device__ float g_vs  [(size_t)Bq*Cc*NS];
__device__ float g_atts[(size_t)Bq*Cc*NS];
__device__ float g_ctx_part[16*32*16*16];
__device__ float g_ctx[16*256];
__device__ float g_ma[(size_t)Bq*C4*NPIX];
__device__ float g_mb[(size_t)Bq*C4*NPIX];

__device__ __forceinline__ float gelu_f(float x){
    return 0.5f * x * (1.0f + erff(x * 0.70710678118654752f));
}

// ---------------- K1: 1x1 conv (64->64) with checkerboard input mask ----------------
// mode 0: keep nonanchor ((y+x)%2==0)  [q];  mode 1: keep anchor [k];  mode 2: keep all [v]
__global__ void k_conv1x1_qkv(const float* __restrict__ x, const float* __restrict__ w,
                              const float* __restrict__ bias, float* __restrict__ out, int mode)
{
    __shared__ float wsm[64*64];            // [ci][co], co contiguous
    int tid = threadIdx.x;
    for (int i = tid; i < 4096; i += 256){
        int co = i & 63, ci = i >> 6;
        wsm[ci*64 + co] = w[co*64 + ci];
    }
    __syncthreads();
    int b   = blockIdx.y;
    int pos = blockIdx.x*256 + tid;
    const float* xp = x + (size_t)b*Cc*NPIX + pos;

    float acc[64];
#pragma unroll
    for (int i = 0; i < 64; i++) acc[i] = 0.f;

    for (int ci = 0; ci < 64; ci++){
        float xv = xp[(size_t)ci*NPIX];
        const float4* w4 = (const float4*)(wsm + ci*64);
#pragma unroll
        for (int c4 = 0; c4 < 16; c4++){
            float4 wv = w4[c4];
            acc[c4*4+0] += wv.x*xv;
            acc[c4*4+1] += wv.y*xv;
            acc[c4*4+2] += wv.z*xv;
            acc[c4*4+3] += wv.w*xv;
        }
    }
    int y = pos >> 8, xc = pos & 255;
    int par = (y ^ xc) & 1;                        // 0 = nonanchor, 1 = anchor
    bool keep = (mode == 2) || (mode == 0 ? par == 0 : par == 1);
    float* op = out + (size_t)b*Cc*NPIX + pos;
#pragma unroll
    for (int co = 0; co < 64; co++){
        float v = keep ? acc[co] + bias[co] : bias[co];
        op[(size_t)co*NPIX] = v;
    }
}

// ---------------- K2: depthwise 3x3 (pad 1) evaluated only at one parity, stored squeezed ----------------
// anchorSel=0: output at nonanchor positions (col = 2j + (r&1));  =1: anchor (col = 2j + 1-(r&1))
__global__ void k_dw3x3_squeeze(const float* __restrict__ in, const float* __restrict__ w,
                                const float* __restrict__ bias, float* __restrict__ out, int anchorSel)
{
    int idx = blockIdx.x*256 + threadIdx.x;        // over B*C*H*W2
    int j = idx & (W2-1);
    int r = (idx >> 7) & (Hh-1);
    int c = (idx >> 15) & (Cc-1);
    int b = idx >> 21;
    int col = 2*j + (anchorSel ? (1 - (r & 1)) : (r & 1));
    const float* ip = in + ((size_t)(b*Cc + c))*NPIX;
    const float* wp = w + c*9;
    float s = bias[c];
#pragma unroll
    for (int dy = -1; dy <= 1; dy++){
        int rr = r + dy;
        if ((unsigned)rr < Hh){
#pragma unroll
            for (int dx = -1; dx <= 1; dx++){
                int cc = col + dx;
                if ((unsigned)cc < Ww)
                    s += wp[(dy+1)*3 + (dx+1)] * ip[rr*Ww + cc];
            }
        }
    }
    out[idx] = s;
}

// ---------------- K3: q softmax over d=16 (within head), in-place on squeezed q ----------------
__global__ void k_softmax_d(float* __restrict__ q)
{
    int idx = blockIdx.x*256 + threadIdx.x;        // over B*NHEAD*NS
    int n  = idx & (NS-1);
    int hd = (idx >> 15) & (NHEAD-1);
    int b  = idx >> 17;
    float* p = q + ((size_t)(b*Cc + hd*Dd))*NS + n;
    float v[16];
    float mx = -1e30f;
#pragma unroll
    for (int d = 0; d < 16; d++){ v[d] = p[(size_t)d*NS]; mx = fmaxf(mx, v[d]); }
    float s = 0.f;
#pragma unroll
    for (int d = 0; d < 16; d++){ v[d] = __expf(v[d]-mx); s += v[d]; }
    float inv = 1.f/s;
#pragma unroll
    for (int d = 0; d < 16; d++) p[(size_t)d*NS] = v[d]*inv;
}

// ---------------- K4: k softmax over N=32768 per (b,c) row, in-place ----------------
__global__ void k_softmax_n(float* __restrict__ kk)
{
    int row = blockIdx.x;                          // B*C = 256 rows
    float* p = kk + (size_t)row*NS;
    int tid = threadIdx.x;
    __shared__ float red[256];
    float mx = -1e30f;
    for (int i = tid; i < NS; i += 256) mx = fmaxf(mx, p[i]);
    red[tid] = mx; __syncthreads();
    for (int s = 128; s > 0; s >>= 1){ if (tid < s) red[tid] = fmaxf(red[tid], red[tid+s]); __syncthreads(); }
    mx = red[0]; __syncthreads();
    float sum = 0.f;
    for (int i = tid; i < NS; i += 256) sum += __expf(p[i]-mx);
    red[tid] = sum; __syncthreads();
    for (int s = 128; s > 0; s >>= 1){ if (tid < s) red[tid] += red[tid+s]; __syncthreads(); }
    float inv = 1.f/red[0];
    for (int i = tid; i < NS; i += 256) p[i] = __expf(p[i]-mx)*inv;
}

// ---------------- K5: ctx partials: ctx[d][e] = sum_n ksm[d,n]*vs[e,n]  (per b,head, N-chunked) ----------------
__global__ void k_ctx_part(const float* __restrict__ ks, const float* __restrict__ vs,
                           float* __restrict__ part)
{
    int bh = blockIdx.y;                           // 16
    int chunk = blockIdx.x;                        // 32 chunks of 1024
    int e    = threadIdx.x >> 5;                   // warp id = e
    int lane = threadIdx.x & 31;
    int b = bh >> 2, hd = bh & 3;
    const float* kp = ks + ((size_t)(b*Cc + hd*Dd))*NS;
    const float* vp = vs + ((size_t)(b*Cc + hd*Dd + e))*NS;
    float acc[16];
#pragma unroll
    for (int d = 0; d < 16; d++) acc[d] = 0.f;
    int n0 = chunk*1024;
    for (int n = n0 + lane; n < n0 + 1024; n += 32){
        float vv = vp[n];
#pragma unroll
        for (int d = 0; d < 16; d++) acc[d] += kp[(size_t)d*NS + n]*vv;
    }
#pragma unroll
    for (int d = 0; d < 16; d++){
#pragma unroll
        for (int off = 16; off; off >>= 1) acc[d] += __shfl_xor_sync(0xffffffffu, acc[d], off);
    }
    if (lane == 0){
#pragma unroll
        for (int d = 0; d < 16; d++)
            part[(((size_t)bh*32 + chunk)*16 + e)*16 + d] = acc[d];
    }
}

__global__ void k_ctx_reduce(const float* __restrict__ part, float* __restrict__ ctx)
{
    int bh = blockIdx.x, t = threadIdx.x;          // t = e*16+d
    int e = t >> 4, d = t & 15;
    float s = 0.f;
    for (int ch = 0; ch < 32; ch++) s += part[(((size_t)bh*32 + ch)*16 + e)*16 + d];
    ctx[bh*256 + d*16 + e] = s;                    // stored [d][e]
}

// ---------------- K6: att[e,n] = sum_d ctx[d,e]*qsm[d,n]  (compact squeezed output) ----------------
__global__ void k_att(const float* __restrict__ q, const float* __restrict__ ctx,
                      float* __restrict__ atts)
{
    int bh = blockIdx.y;
    __shared__ float csm[256];
    for (int i = threadIdx.x; i < 256; i += 128) csm[i] = ctx[bh*256 + i];
    __syncthreads();
    int n = blockIdx.x*128 + threadIdx.x;
    int b = bh >> 2, hd = bh & 3;
    const float* qp = q + ((size_t)(b*Cc + hd*Dd))*NS + n;
    float qv[16];
#pragma unroll
    for (int d = 0; d < 16; d++) qv[d] = qp[(size_t)d*NS];
    float o[16];
#pragma unroll
    for (int e = 0; e < 16; e++) o[e] = 0.f;
#pragma unroll
    for (int d = 0; d < 16; d++){
        float qd = qv[d];
#pragma unroll
        for (int e = 0; e < 16; e++) o[e] += csm[d*16 + e]*qd;
    }
    float* op = atts + ((size_t)(b*Cc + hd*Dd))*NS + n;
#pragma unroll
    for (int e = 0; e < 16; e++) op[(size_t)e*NS] = o[e];
}

// ---------------- K7: 5x5 conv 64->128 (pad 2) reading compact checkerboard input ----------------
// att full-image is zero at anchor; nonanchor value at (iy,ix) lives at atts[.., iy, ix>>1].
// Each thread owns an (even,odd) output column pair; tap parity t=(ky+kx)&1 routes to accU/accV.
__global__ void k_conv5x5(const float* __restrict__ atts, const float* __restrict__ rw,
                          const float* __restrict__ rb, float* __restrict__ out)
{
    int z = blockIdx.z;  int b = z >> 3;  int coBase = (z & 7)*16;
    int wBase = blockIdx.x*32;
    int hBase = blockIdx.y*16;
    int tid = threadIdx.x;                          // 256
    int px = tid & 15, yl = tid >> 4;
    int y  = hBase + yl;
    int x0 = wBase + 2*px;                          // even
    int py = y & 1;

    __shared__ float insm[20*18];
    __shared__ float wsm[25*16];                    // [tap][co]
    int jBase = (wBase >> 1) - 1;

    float accU[16], accV[16];
#pragma unroll
    for (int i = 0; i < 16; i++){ accU[i] = 0.f; accV[i] = 0.f; }

    for (int ci = 0; ci < 64; ci++){
        __syncthreads();
        for (int i = tid; i < 360; i += 256){
            int rr = i/18, jj = i - rr*18;
            int gy = hBase - 2 + rr;
            int gj = jBase + jj;
            float v = 0.f;
            if ((unsigned)gy < Hh && (unsigned)gj < W2)
                v = atts[(((size_t)(b*Cc + ci))*Hh + gy)*W2 + gj];
            insm[rr*18 + jj] = v;
        }
        for (int i = tid; i < 400; i += 256){
            int tap = i >> 4, co = i & 15;
            wsm[tap*16 + co] = rw[((size_t)(coBase + co)*64 + ci)*25 + tap];
        }
        __syncthreads();
#pragma unroll
        for (int ky = 0; ky < 5; ky++){
#pragma unroll
            for (int kx = 0; kx < 5; kx++){
                const int t = (ky + kx) & 1;        // compile-time
                int s  = t ^ py;
                int ix = x0 + s + kx - 2;
                int rr = yl + ky;
                int jj = (ix >> 1) - jBase;
                float iv = insm[rr*18 + jj];
                const float4* w4 = (const float4*)(wsm + (ky*5 + kx)*16);
                if (t == 0){
#pragma unroll
                    for (int c4 = 0; c4 < 4; c4++){
                        float4 wv = w4[c4];
                        accU[c4*4+0] += wv.x*iv; accU[c4*4+1] += wv.y*iv;
                        accU[c4*4+2] += wv.z*iv; accU[c4*4+3] += wv.w*iv;
                    }
                } else {
#pragma unroll
                    for (int c4 = 0; c4 < 4; c4++){
                        float4 wv = w4[c4];
                        accV[c4*4+0] += wv.x*iv; accV[c4*4+1] += wv.y*iv;
                        accV[c4*4+2] += wv.z*iv; accV[c4*4+3] += wv.w*iv;
                    }
                }
            }
        }
    }
    // accU -> column x0+py, accV -> column x0+1-py
#pragma unroll
    for (int co = 0; co < 16; co++){
        float bv = rb[coBase + co];
        size_t base = (((size_t)(b*C2 + coBase + co))*Hh + y)*Ww;
        out[base + x0 + py]       = accU[co] + bv;
        out[base + x0 + 1 - py]   = accV[co] + bv;
    }
}

// ---------------- K8: m1 1x1 conv 128->256 + exact gelu ----------------
__global__ void k_m1(const float* __restrict__ in, const float* __restrict__ w,
                     const float* __restrict__ bias, float* __restrict__ out)
{
    __shared__ float wsm[128*64];                   // [ci][co]
    int z = blockIdx.y;  int b = z >> 2;  int coBase = (z & 3)*64;
    int tid = threadIdx.x;
    for (int i = tid; i < 8192; i += 256){
        int co = i & 63, ci = i >> 6;
        wsm[ci*64 + co] = w[(size_t)(coBase + co)*C2 + ci];
    }
    __syncthreads();
    int pos = blockIdx.x*256 + tid;
    const float* xp = in + (size_t)b*C2*NPIX + pos;
    float acc[64];
#pragma unroll
    for (int i = 0; i < 64; i++) acc[i] = 0.f;
    for (int ci = 0; ci < 128; ci++){
        float xv = xp[(size_t)ci*NPIX];
        const float4* w4 = (const float4*)(wsm + ci*64);
#pragma unroll
        for (int c4 = 0; c4 < 16; c4++){
            float4 wv = w4[c4];
            acc[c4*4+0] += wv.x*xv; acc[c4*4+1] += wv.y*xv;
            acc[c4*4+2] += wv.z*xv; acc[c4*4+3] += wv.w*xv;
        }
    }
    float* op = out + (size_t)b*C4*NPIX + pos;
#pragma unroll
    for (int co = 0; co < 64; co++)
        op[(size_t)(coBase + co)*NPIX] = gelu_f(acc[co] + bias[coBase + co]);
}

// ---------------- K9: m2 depthwise 3x3 (C4 channels, pad 1) + gelu ----------------
__global__ void k_dw3x3_gelu(const float* __restrict__ in, const float* __restrict__ w,
                             const float* __restrict__ bias, float* __restrict__ out)
{
    int idx = blockIdx.x*256 + threadIdx.x;        // over B*C4*NPIX = 2^26
    int x = idx & 255;
    int y = (idx >> 8) & 255;
    int c = (idx >> 16) & 255;
    int b = idx >> 24;
    const float* ip = in + ((size_t)(b*C4 + c))*NPIX;
    const float* wp = w + c*9;
    float s = bias[c];
#pragma unroll
    for (int dy = -1; dy <= 1; dy++){
        int rr = y + dy;
        if ((unsigned)rr < Hh){
#pragma unroll
            for (int dx = -1; dx <= 1; dx++){
                int cc = x + dx;
                if ((unsigned)cc < Ww)
                    s += wp[(dy+1)*3 + (dx+1)] * ip[rr*Ww + cc];
            }
        }
    }
    out[idx] = gelu_f(s);
}

// ---------------- K10: m3 1x1 conv 256->128 + residual add into d_out ----------------
__global__ void k_m3_add(const float* __restrict__ in, const float* __restrict__ w,
                         const float* __restrict__ bias, float* __restrict__ out)
{
    __shared__ float wsm[128*64];
    int z = blockIdx.y;  int b = z >> 1;  int coBase = (z & 1)*64;
    int tid = threadIdx.x;
    int pos = blockIdx.x*256 + tid;
    const float* xp = in + (size_t)b*C4*NPIX + pos;
    float acc[64];
#pragma unroll
    for (int i = 0; i < 64; i++) acc[i] = 0.f;
    for (int stage = 0; stage < 2; stage++){
        __syncthreads();
        for (int i = tid; i < 8192; i += 256){
            int co = i & 63, ci = i >> 6;
            wsm[ci*64 + co] = w[(size_t)(coBase + co)*C4 + stage*128 + ci];
        }
        __syncthreads();
        for (int ci = 0; ci < 128; ci++){
            float xv = xp[(size_t)(stage*128 + ci)*NPIX];
            const float4* w4 = (const float4*)(wsm + ci*64);
#pragma unroll
            for (int c4 = 0; c4 < 16; c4++){
                float4 wv = w4[c4];
                acc[c4*4+0] += wv.x*xv; acc[c4*4+1] += wv.y*xv;
                acc[c4*4+2] += wv.z*xv; acc[c4*4+3] += wv.w*xv;
            }
        }
    }
    float* op = out + (size_t)b*C2*NPIX + pos;
#pragma unroll
    for (int co = 0; co < 64; co++){
        size_t o = (size_t)(coBase + co)*NPIX;
        op[o] = op[o] + acc[co] + bias[coBase + co];   // attention + m
    }
}

// ---------------- launch ----------------
extern "C" void kernel_launch(void* const* d_in, const int* in_sizes, int n_in,
                              void* d_out, int out_size)
{
    (void)in_sizes; (void)n_in; (void)out_size;
    const float* x1   = (const float*)d_in[0];
    const float* x2   = (const float*)d_in[1];
    const float* q1_w = (const float*)d_in[2];
    const float* q1_b = (const float*)d_in[3];
    const float* q2_w = (const float*)d_in[4];
    const float* q2_b = (const float*)d_in[5];
    const float* k1_w = (const float*)d_in[6];
    const float* k1_b = (const float*)d_in[7];
    const float* k2_w = (const float*)d_in[8];
    const float* k2_b = (const float*)d_in[9];
    const float* v1_w = (const float*)d_in[10];
    const float* v1_b = (const float*)d_in[11];
    const float* v2_w = (const float*)d_in[12];
    const float* v2_b = (const float*)d_in[13];
    const float* r_w  = (const float*)d_in[14];
    const float* r_b  = (const float*)d_in[15];
    const float* m1_w = (const float*)d_in[16];
    const float* m1_b = (const float*)d_in[17];
    const float* m2_w = (const float*)d_in[18];
    const float* m2_b = (const float*)d_in[19];
    const float* m3_w = (const float*)d_in[20];
    const float* m3_b = (const float*)d_in[21];
    float* out = (float*)d_out;

    float *qpre, *kpre, *vpre, *qs, *ks, *vs, *atts, *part, *ctx, *ma, *mb;
    cudaGetSymbolAddress((void**)&qpre, g_qpre);
    cudaGetSymbolAddress((void**)&kpre, g_kpre);
    cudaGetSymbolAddress((void**)&vpre, g_vpre);
    cudaGetSymbolAddress((void**)&qs,   g_qs);
    cudaGetSymbolAddress((void**)&ks,   g_ks);
    cudaGetSymbolAddress((void**)&vs,   g_vs);
    cudaGetSymbolAddress((void**)&atts, g_atts);
    cudaGetSymbolAddress((void**)&part, g_ctx_part);
    cudaGetSymbolAddress((void**)&ctx,  g_ctx);
    cudaGetSymbolAddress((void**)&ma,   g_ma);
    cudaGetSymbolAddress((void**)&mb,   g_mb);

    k_conv1x1_qkv<<<dim3(NPIX/256, Bq), 256>>>(x1, q1_w, q1_b, qpre, 0);
    k_conv1x1_qkv<<<dim3(NPIX/256, Bq), 256>>>(x1, k1_w, k1_b, kpre, 1);
    k_conv1x1_qkv<<<dim3(NPIX/256, Bq), 256>>>(x2, v1_w, v1_b, vpre, 2);

    k_dw3x3_squeeze<<<(Bq*Cc*Hh*W2)/256, 256>>>(qpre, q2_w, q2_b, qs, 0);
    k_dw3x3_squeeze<<<(Bq*Cc*Hh*W2)/256, 256>>>(kpre, k2_w, k2_b, ks, 1);
    k_dw3x3_squeeze<<<(Bq*Cc*Hh*W2)/256, 256>>>(vpre, v2_w, v2_b, vs, 1);

    k_softmax_d<<<(Bq*NHEAD*NS)/256, 256>>>(qs);
    k_softmax_n<<<Bq*Cc, 256>>>(ks);

    k_ctx_part<<<dim3(32, Bq*NHEAD), 512>>>(ks, vs, part);
    k_ctx_reduce<<<Bq*NHEAD, 256>>>(part, ctx);

    k_att<<<dim3(NS/128, Bq*NHEAD), 128>>>(qs, ctx, atts);

    k_conv5x5<<<dim3(Ww/32, Hh/16, Bq*(C2/16)), 256>>>(atts, r_w, r_b, out);

    k_m1<<<dim3(NPIX/256, Bq*4), 256>>>(out, m1_w, m1_b, ma);
    k_dw3x3_gelu<<<(Bq*C4*NPIX)/256, 256>>>(ma, m2_w, m2_b, mb);
    k_m3_add<<<dim3(NPIX/256, Bq*2), 256>>>(mb, m3_w, m3_b, out);
}